// round 16
// baseline (speedup 1.0000x reference)
#include <cuda_runtime.h>
#include <cuda_bf16.h>
#include <cuda_fp16.h>
#include <math.h>

#define D_MODEL   1024
#define NUM_HEADS 16
#define HEAD_DIM  64
#define BATCH     4
#define SEQ       2048
#define M_TOTAL   (BATCH * SEQ)   // 8192
#define NQKV      (3 * D_MODEL)   // 3072
#define NBH       (BATCH * NUM_HEADS)  // 64

// ============================================================================
// Device global scratch (allocation-free rule)
// ============================================================================
__device__ __half g_X[M_TOTAL * D_MODEL];        // X fp16, [m][k]
__device__ __half g_Bqkv[D_MODEL * NQKV];        // [k][n] fp16
__device__ __half g_Wo2[D_MODEL * D_MODEL];      // [k][n] fp16
__device__ float g_bias_qkv[NQKV];
__device__ __half g_q[NBH * SEQ * HEAD_DIM];     // Q fp16 (pre-scaled x 0.125*log2e)
__device__ __half g_k[NBH * SEQ * HEAD_DIM];     // K fp16
__device__ __half g_v[NBH * SEQ * HEAD_DIM];     // V fp16
__device__ __half g_A2[M_TOTAL * D_MODEL];       // attn out fp16, [m][k]

// ============================================================================
// PTX helpers (portable, compute_103-safe)
// ============================================================================
__device__ __forceinline__ unsigned smem_u32(const void* p) {
    unsigned a;
    asm("{ .reg .u64 t; cvta.to.shared.u64 t, %1; cvt.u32.u64 %0, t; }"
        : "=r"(a) : "l"(p));
    return a;
}
__device__ __forceinline__ void ldm_x4(unsigned* r, unsigned addr) {
    asm volatile("ldmatrix.sync.aligned.m8n8.x4.shared.b16 {%0,%1,%2,%3}, [%4];"
        : "=r"(r[0]), "=r"(r[1]), "=r"(r[2]), "=r"(r[3]) : "r"(addr));
}
__device__ __forceinline__ void ldm_x4_t(unsigned* r, unsigned addr) {
    asm volatile("ldmatrix.sync.aligned.m8n8.x4.trans.shared.b16 {%0,%1,%2,%3}, [%4];"
        : "=r"(r[0]), "=r"(r[1]), "=r"(r[2]), "=r"(r[3]) : "r"(addr));
}
__device__ __forceinline__ void mma16816h(float* c, const unsigned* a, const unsigned* b) {
    asm volatile("mma.sync.aligned.m16n8k16.row.col.f32.f16.f16.f32 "
        "{%0,%1,%2,%3}, {%4,%5,%6,%7}, {%8,%9}, {%0,%1,%2,%3};"
        : "+f"(c[0]), "+f"(c[1]), "+f"(c[2]), "+f"(c[3])
        : "r"(a[0]), "r"(a[1]), "r"(a[2]), "r"(a[3]), "r"(b[0]), "r"(b[1]));
}
__device__ __forceinline__ void cp_async16(unsigned saddr, const void* gptr) {
    asm volatile("cp.async.cg.shared.global [%0], [%1], 16;"
                 :: "r"(saddr), "l"(gptr) : "memory");
}
#define CP_COMMIT() asm volatile("cp.async.commit_group;" ::: "memory")
#define CP_WAIT(N)  asm volatile("cp.async.wait_group %0;" :: "n"(N) : "memory")

__device__ __forceinline__ unsigned pack_h2(float lo, float hi) {
    __half2 h = __floats2half2_rn(lo, hi);
    return *reinterpret_cast<unsigned*>(&h);
}
__device__ __forceinline__ float ex2(float x) {
    float y;
    asm("ex2.approx.f32 %0, %1;" : "=f"(y) : "f"(x));
    return y;
}

// ============================================================================
// Fused conversion kernel: one launch, blockIdx-partitioned, fully coalesced.
// ============================================================================
#define CONV_X_BLKS   ((M_TOTAL * D_MODEL) / 1024)   // 8192
#define CONV_B_BLKS   ((NQKV * D_MODEL) / 1024)      // 3072
#define CONV_WO_BLKS  ((D_MODEL * D_MODEL) / 1024)   // 1024
#define CONV_BLKS     (CONV_X_BLKS + CONV_B_BLKS + CONV_WO_BLKS)

__global__ __launch_bounds__(256) void conv_all(
    const float* __restrict__ x,
    const float* __restrict__ Wq, const float* __restrict__ bq,
    const float* __restrict__ Wk, const float* __restrict__ bk,
    const float* __restrict__ Wv, const float* __restrict__ bv,
    const float* __restrict__ Wo)
{
    const int b = blockIdx.x;
    if (b < CONV_X_BLKS) {
        size_t i = ((size_t)b * 256 + threadIdx.x) * 4;
        float4 v = *reinterpret_cast<const float4*>(x + i);
        uint2 o;
        o.x = pack_h2(v.x, v.y);
        o.y = pack_h2(v.z, v.w);
        *reinterpret_cast<uint2*>(g_X + i) = o;
    } else if (b < CONV_X_BLKS + CONV_B_BLKS) {
        size_t j = ((size_t)(b - CONV_X_BLKS) * 256 + threadIdx.x) * 4;
        const int e = (int)(j & 63);
        const int k = (int)((j >> 6) & 1023);
        const int h = (int)((j >> 16) & 15);
        const int proj = (int)(j >> 20);
        const float* W = (proj == 0) ? Wq : (proj == 1) ? Wk : Wv;
        float4 v = *reinterpret_cast<const float4*>(
            W + (((size_t)h * D_MODEL + k) << 6) + e);
        const int n = proj * 1024 + h * 64 + e;
        uint2 o;
        o.x = pack_h2(v.x, v.y);
        o.y = pack_h2(v.z, v.w);
        *reinterpret_cast<uint2*>(g_Bqkv + (size_t)k * NQKV + n) = o;
        if (k == 0) {
            const float* bb = (proj == 0) ? bq : (proj == 1) ? bk : bv;
            #pragma unroll
            for (int jj = 0; jj < 4; jj++)
                g_bias_qkv[n + jj] = bb[h * 64 + e + jj];
        }
    } else {
        size_t i = ((size_t)(b - CONV_X_BLKS - CONV_B_BLKS) * 256 + threadIdx.x) * 4;
        float4 v = *reinterpret_cast<const float4*>(Wo + i);
        uint2 o;
        o.x = pack_h2(v.x, v.y);
        o.y = pack_h2(v.z, v.w);
        *reinterpret_cast<uint2*>(g_Wo2 + i) = o;
    }
}

// ============================================================================
// GEMM on mma.sync, single-pass fp16, 2-stage cp.async, BK=64. (unchanged)
// ============================================================================
#define AST 72
#define BST 136
#define MMS_A 0
#define MMS_B 9216
#define STAGE_EL (9216 + 8704)
#define MM_SMEM  (2 * STAGE_EL * 2)       // 71680 B per CTA

// Q pre-scale: 1/sqrt(64) * log2(e)
#define QSCALE 0.18033688011112042f

__global__ __launch_bounds__(256, 2) void mm_mma(const float* __restrict__ bias_ext,
                                                 float* __restrict__ outp, int mode) {
    extern __shared__ __align__(16) __half smm[];
    const unsigned sbase = smem_u32(smm);
    const int tid = threadIdx.x;
    const int lane = tid & 31;
    const int w = tid >> 5;
    const int mw = w >> 2, nw = w & 3;
    const int n0 = blockIdx.x * 128;
    const int m0 = blockIdx.y * 128;

    const __half* __restrict__ Ag = (mode == 1) ? g_X : g_A2;
    const __half* __restrict__ Bg = (mode == 1) ? g_Bqkv : g_Wo2;
    const int bw = (mode == 1) ? NQKV : D_MODEL;
    const float* __restrict__ bias = (mode == 1) ? g_bias_qkv : bias_ext;

    float acc[4][4][4];
    #pragma unroll
    for (int a = 0; a < 4; a++)
        #pragma unroll
        for (int bq_ = 0; bq_ < 4; bq_++)
            #pragma unroll
            for (int c = 0; c < 4; c++) acc[a][bq_][c] = 0.f;

    auto issue = [&](int kc) {
        const int k0 = kc * 64;
        const unsigned sst = sbase + (unsigned)(2 * STAGE_EL) * (kc & 1);
        #pragma unroll
        for (int i = 0; i < 4; i++) {
            const int t = tid + 256 * i;
            {
                const int row = t >> 3, slot = t & 7;
                const unsigned so = 2u * (row * AST + slot * 8);
                const size_t ga = (size_t)(m0 + row) * D_MODEL + k0 + slot * 8;
                cp_async16(sst + 2u * MMS_A + so, Ag + ga);
            }
            {
                const int row = t >> 4, slot = t & 15;
                const unsigned so = 2u * (row * BST + slot * 8);
                const size_t gb = (size_t)(k0 + row) * bw + n0 + slot * 8;
                cp_async16(sst + 2u * MMS_B + so, Bg + gb);
            }
        }
        CP_COMMIT();
    };

    issue(0);

    const int g = lane >> 3;
    for (int kc = 0; kc < 16; kc++) {
        CP_WAIT(0);
        __syncthreads();
        if (kc + 1 < 16) issue(kc + 1);

        const unsigned sst = sbase + (unsigned)(2 * STAGE_EL) * (kc & 1);
        #pragma unroll
        for (int ks = 0; ks < 4; ks++) {
            unsigned ah[4][4], bh[4][2];
            const int arow = mw * 64 + (lane & 15);
            const int acol = ks * 16 + (lane >> 4) * 8;
            #pragma unroll
            for (int mt = 0; mt < 4; mt++) {
                const unsigned off = 2u * ((arow + mt * 16) * AST + acol);
                ldm_x4(ah[mt], sst + 2 * MMS_A + off);
            }
            const int kr = ks * 16 + (g & 1) * 8 + (lane & 7);
            #pragma unroll
            for (int np = 0; np < 2; np++) {
                const unsigned off = 2u * (kr * BST + nw * 32 + np * 16 + (g >> 1) * 8);
                ldm_x4_t(&bh[np * 2][0], sst + 2 * MMS_B + off);
            }
            #pragma unroll
            for (int mt = 0; mt < 4; mt++)
                #pragma unroll
                for (int nt = 0; nt < 4; nt++)
                    mma16816h(acc[mt][nt], ah[mt], bh[nt]);
        }
    }

    // Epilogue
    #pragma unroll
    for (int mt = 0; mt < 4; mt++) {
        const int r0 = m0 + mw * 64 + mt * 16 + (lane >> 2);
        #pragma unroll
        for (int nt = 0; nt < 4; nt++) {
            const int c = n0 + nw * 32 + nt * 8 + (lane & 3) * 2;
            const float b0 = bias[c], b1 = bias[c + 1];
            #pragma unroll
            for (int h2 = 0; h2 < 2; h2++) {
                const int r = r0 + h2 * 8;
                float v0 = acc[mt][nt][h2 * 2 + 0] + b0;
                float v1 = acc[mt][nt][h2 * 2 + 1] + b1;
                if (mode == 0) {
                    float2 vv = make_float2(v0, v1);
                    *reinterpret_cast<float2*>(outp + (size_t)r * D_MODEL + c) = vv;
                } else {
                    const int proj = c >> 10, nc = c & 1023, hh = nc >> 6, e = nc & 63;
                    const size_t idx =
                        (((size_t)((r >> 11) * NUM_HEADS + hh)) * SEQ + (r & 2047)) * HEAD_DIM + e;
                    if (proj == 0) {
                        *reinterpret_cast<unsigned*>(g_q + idx) =
                            pack_h2(v0 * QSCALE, v1 * QSCALE);
                    } else if (proj == 1) {
                        *reinterpret_cast<unsigned*>(g_k + idx) = pack_h2(v0, v1);
                    } else {
                        *reinterpret_cast<unsigned*>(g_v + idx) = pack_h2(v0, v1);
                    }
                }
            }
        }
    }
}

// ============================================================================
// Flash attention, FA2-style, 2 CTAs/SM: 128 q-rows x 128-key tiles.
// One barrier + one softmax update per 128 keys. exp via raw ex2.approx
// (log2e folded into Q pre-scale; m,l tracked in log2 domain).
// smem: Q 18.4KB + K 2x18.4KB + V 2x18.4KB = 92.2KB/CTA.
// ============================================================================
#define TST 72
#define AQ 0
#define AK(s) (9216 + (s) * 9216)
#define AV(s) (27648 + (s) * 9216)
#define ATTN_SMEM (46080 * 2)   // 92160 B

__global__ __launch_bounds__(256, 2) void attn_mma() {
    extern __shared__ __align__(16) __half smm[];
    const unsigned sbase = smem_u32(smm);
    const int tid = threadIdx.x;
    const int lane = tid & 31;
    const int w = tid >> 5;
    const int q0 = blockIdx.x * 128;
    const int bh = blockIdx.y;
    const size_t gbase = (size_t)bh * SEQ * HEAD_DIM;

    const int g = lane >> 3;
    const int browo = (g >> 1) * 8 + (lane & 7);
    const int bko = (g & 1) * 8;

    auto issueKV = [&](int kt2) {
        const int t0 = kt2 * 128;
        const int s = kt2 & 1;
        #pragma unroll
        for (int i = 0; i < 4; i++) {
            const int t = tid + 256 * i;
            const int row = t >> 3, slot = t & 7;
            const unsigned so = 2u * (row * TST + slot * 8);
            const size_t gk = gbase + (size_t)(t0 + row) * HEAD_DIM + slot * 8;
            cp_async16(sbase + 2u * AK(s) + so, g_k + gk);
            cp_async16(sbase + 2u * AV(s) + so, g_v + gk);
        }
        CP_COMMIT();
    };

    issueKV(0);

    // stage Q into smem
    #pragma unroll
    for (int i = 0; i < 4; i++) {
        const int t = tid + 256 * i;
        const int row = t >> 3, slot = t & 7;
        const int so = row * TST + slot * 8;
        const size_t gq = gbase + (size_t)(q0 + row) * HEAD_DIM + slot * 8;
        *reinterpret_cast<float4*>(smm + AQ + so) = *reinterpret_cast<const float4*>(g_q + gq);
    }
    __syncthreads();

    // warp's Q fragments (persistent in registers)
    unsigned qf[4][4];
    {
        const int arow = w * 16 + (lane & 15);
        #pragma unroll
        for (int ks = 0; ks < 4; ks++) {
            const unsigned qoff = 2u * (arow * TST + ks * 16 + (lane >> 4) * 8);
            ldm_x4(qf[ks], sbase + 2 * AQ + qoff);
        }
    }

    float m_run[2] = {-INFINITY, -INFINITY};   // log2 domain
    float l_run[2] = {0.f, 0.f};
    float oacc[8][4];
    #pragma unroll
    for (int a = 0; a < 8; a++)
        #pragma unroll
        for (int c = 0; c < 4; c++) oacc[a][c] = 0.f;

    for (int kt = 0; kt < 16; kt++) {
        CP_WAIT(0);        // K[kt] and V[kt] landed
        __syncthreads();   // visible; prev-tile smem fully consumed

        if (kt < 15) issueKV(kt + 1);   // overlaps S + softmax + PV

        const unsigned sk = sbase + 2u * AK(kt & 1);
        const unsigned sv = sbase + 2u * AV(kt & 1);

        // ---- S = Q K^T : 16 n8-tiles over 128 keys ----
        float sacc[16][4];
        #pragma unroll
        for (int a = 0; a < 16; a++)
            #pragma unroll
            for (int c = 0; c < 4; c++) sacc[a][c] = 0.f;

        #pragma unroll
        for (int ks = 0; ks < 4; ks++) {
            #pragma unroll
            for (int kb = 0; kb < 8; kb++) {
                unsigned kh4[4];
                const unsigned off = 2u * ((kb * 16 + browo) * TST + ks * 16 + bko);
                ldm_x4(kh4, sk + off);
                #pragma unroll
                for (int j = 0; j < 2; j++)
                    mma16816h(sacc[kb * 2 + j], qf[ks], &kh4[2 * j]);
            }
        }

        // ---- softmax update (once per 128 keys; log2 domain, ex2) ----
        float mx0 = -INFINITY, mx1 = -INFINITY;
        #pragma unroll
        for (int nt = 0; nt < 16; nt++) {
            mx0 = fmaxf(mx0, fmaxf(sacc[nt][0], sacc[nt][1]));
            mx1 = fmaxf(mx1, fmaxf(sacc[nt][2], sacc[nt][3]));
        }
        mx0 = fmaxf(mx0, __shfl_xor_sync(0xffffffffu, mx0, 1));
        mx0 = fmaxf(mx0, __shfl_xor_sync(0xffffffffu, mx0, 2));
        mx1 = fmaxf(mx1, __shfl_xor_sync(0xffffffffu, mx1, 1));
        mx1 = fmaxf(mx1, __shfl_xor_sync(0xffffffffu, mx1, 2));
        const float mn0 = fmaxf(m_run[0], mx0);
        const float mn1 = fmaxf(m_run[1], mx1);
        const float al0 = ex2(m_run[0] - mn0);
        const float al1 = ex2(m_run[1] - mn1);
        m_run[0] = mn0; m_run[1] = mn1;

        // p = ex2(s - m), pack to fp16 A-fragments, row sums
        unsigned ph[8][4];
        float s0 = 0.f, s1 = 0.f;
        #pragma unroll
        for (int ks = 0; ks < 8; ks++) {
            #pragma unroll
            for (int j = 0; j < 2; j++) {
                const int nt = ks * 2 + j;
                const float p0 = ex2(sacc[nt][0] - mn0);
                const float p1 = ex2(sacc[nt][1] - mn0);
                const float p2 = ex2(sacc[nt][2] - mn1);
                const float p3 = ex2(sacc[nt][3] - mn1);
                s0 += p0 + p1;
                s1 += p2 + p3;
                ph[ks][2 * j + 0] = pack_h2(p0, p1);
                ph[ks][2 * j + 1] = pack_h2(p2, p3);
            }
        }
        s0 += __shfl_xor_sync(0xffffffffu, s0, 1);
        s0 += __shfl_xor_sync(0xffffffffu, s0, 2);
        s1 += __shfl_xor_sync(0xffffffffu, s1, 1);
        s1 += __shfl_xor_sync(0xffffffffu, s1, 2);
        l_run[0] = l_run[0] * al0 + s0;
        l_run[1] = l_run[1] * al1 + s1;
        #pragma unroll
        for (int ot = 0; ot < 8; ot++) {
            oacc[ot][0] *= al0; oacc[ot][1] *= al0;
            oacc[ot][2] *= al1; oacc[ot][3] *= al1;
        }

        // ---- O += P V : contraction over 128 keys ----
        #pragma unroll
        for (int ks = 0; ks < 8; ks++) {
            const int kr = ks * 16 + (g & 1) * 8 + (lane & 7);
            #pragma unroll
            for (int eb = 0; eb < 4; eb++) {
                unsigned vh4[4];
                const unsigned voff = 2u * (kr * TST + eb * 16 + (g >> 1) * 8);
                ldm_x4_t(vh4, sv + voff);
                #pragma unroll
                for (int j = 0; j < 2; j++)
                    mma16816h(oacc[eb * 2 + j], ph[ks], &vh4[2 * j]);
            }
        }
    }

    // Epilogue: normalize, write single-fp16 A2 (concat layout)
    const int bb = bh >> 4, hh = bh & 15;
    const int r0 = w * 16 + (lane >> 2);
    const float inv0 = 1.f / l_run[0];
    const float inv1 = 1.f / l_run[1];
    const size_t mrow0 = ((size_t)bb * SEQ + q0 + r0) * D_MODEL + hh * HEAD_DIM;
    const size_t mrow1 = ((size_t)bb * SEQ + q0 + r0 + 8) * D_MODEL + hh * HEAD_DIM;
    #pragma unroll
    for (int ot = 0; ot < 8; ot++) {
        const int e = ot * 8 + (lane & 3) * 2;
        *reinterpret_cast<unsigned*>(g_A2 + mrow0 + e) =
            pack_h2(oacc[ot][0] * inv0, oacc[ot][1] * inv0);
        *reinterpret_cast<unsigned*>(g_A2 + mrow1 + e) =
            pack_h2(oacc[ot][2] * inv1, oacc[ot][3] * inv1);
    }
}

// ============================================================================
extern "C" void kernel_launch(void* const* d_in, const int* in_sizes, int n_in,
                              void* d_out, int out_size)
{
    const float* x  = (const float*)d_in[0];
    const float* Wq = (const float*)d_in[1];
    const float* bq = (const float*)d_in[2];
    const float* Wk = (const float*)d_in[3];
    const float* bk = (const float*)d_in[4];
    const float* Wv = (const float*)d_in[5];
    const float* bv = (const float*)d_in[6];
    const float* Wo = (const float*)d_in[7];
    const float* bo = (const float*)d_in[8];
    float* out = (float*)d_out;

    cudaFuncSetAttribute(mm_mma, cudaFuncAttributeMaxDynamicSharedMemorySize, MM_SMEM);
    cudaFuncSetAttribute(attn_mma, cudaFuncAttributeMaxDynamicSharedMemorySize, ATTN_SMEM);

    conv_all<<<CONV_BLKS, 256>>>(x, Wq, bq, Wk, bk, Wv, bv, Wo);

    mm_mma<<<dim3(NQKV / 128, M_TOTAL / 128), 256, MM_SMEM>>>(nullptr, nullptr, 1);
    attn_mma<<<dim3(SEQ / 128, NBH), 256, ATTN_SMEM>>>();
    mm_mma<<<dim3(D_MODEL / 128, M_TOTAL / 128), 256, MM_SMEM>>>(bo, out, 0);
}

// round 17
// speedup vs baseline: 1.0700x; 1.0700x over previous
#include <cuda_runtime.h>
#include <cuda_bf16.h>
#include <cuda_fp16.h>
#include <math.h>

#define D_MODEL   1024
#define NUM_HEADS 16
#define HEAD_DIM  64
#define BATCH     4
#define SEQ       2048
#define M_TOTAL   (BATCH * SEQ)   // 8192
#define NQKV      (3 * D_MODEL)   // 3072
#define NBH       (BATCH * NUM_HEADS)  // 64

// ============================================================================
// Device global scratch (allocation-free rule)
// ============================================================================
__device__ __half g_X[M_TOTAL * D_MODEL];        // X fp16, [m][k]
__device__ __half g_Bqkv[D_MODEL * NQKV];        // [k][n] fp16
__device__ __half g_Wo2[D_MODEL * D_MODEL];      // [k][n] fp16
__device__ float g_bias_qkv[NQKV];
__device__ __half g_q[NBH * SEQ * HEAD_DIM];     // Q fp16 (pre-scaled x 0.125*log2e)
__device__ __half g_k[NBH * SEQ * HEAD_DIM];     // K fp16
__device__ __half g_v[NBH * SEQ * HEAD_DIM];     // V fp16
__device__ __half g_A2[M_TOTAL * D_MODEL];       // attn out fp16, [m][k]

// ============================================================================
// PTX helpers (portable, compute_103-safe)
// ============================================================================
__device__ __forceinline__ unsigned smem_u32(const void* p) {
    unsigned a;
    asm("{ .reg .u64 t; cvta.to.shared.u64 t, %1; cvt.u32.u64 %0, t; }"
        : "=r"(a) : "l"(p));
    return a;
}
__device__ __forceinline__ void ldm_x4(unsigned* r, unsigned addr) {
    asm volatile("ldmatrix.sync.aligned.m8n8.x4.shared.b16 {%0,%1,%2,%3}, [%4];"
        : "=r"(r[0]), "=r"(r[1]), "=r"(r[2]), "=r"(r[3]) : "r"(addr));
}
__device__ __forceinline__ void ldm_x4_t(unsigned* r, unsigned addr) {
    asm volatile("ldmatrix.sync.aligned.m8n8.x4.trans.shared.b16 {%0,%1,%2,%3}, [%4];"
        : "=r"(r[0]), "=r"(r[1]), "=r"(r[2]), "=r"(r[3]) : "r"(addr));
}
__device__ __forceinline__ void mma16816h(float* c, const unsigned* a, const unsigned* b) {
    asm volatile("mma.sync.aligned.m16n8k16.row.col.f32.f16.f16.f32 "
        "{%0,%1,%2,%3}, {%4,%5,%6,%7}, {%8,%9}, {%0,%1,%2,%3};"
        : "+f"(c[0]), "+f"(c[1]), "+f"(c[2]), "+f"(c[3])
        : "r"(a[0]), "r"(a[1]), "r"(a[2]), "r"(a[3]), "r"(b[0]), "r"(b[1]));
}
__device__ __forceinline__ void cp_async16(unsigned saddr, const void* gptr) {
    asm volatile("cp.async.cg.shared.global [%0], [%1], 16;"
                 :: "r"(saddr), "l"(gptr) : "memory");
}
#define CP_COMMIT() asm volatile("cp.async.commit_group;" ::: "memory")
#define CP_WAIT(N)  asm volatile("cp.async.wait_group %0;" :: "n"(N) : "memory")

__device__ __forceinline__ unsigned pack_h2(float lo, float hi) {
    __half2 h = __floats2half2_rn(lo, hi);
    return *reinterpret_cast<unsigned*>(&h);
}
__device__ __forceinline__ float ex2(float x) {
    float y;
    asm("ex2.approx.f32 %0, %1;" : "=f"(y) : "f"(x));
    return y;
}

// ============================================================================
// Fused conversion kernel (unchanged from R15)
// ============================================================================
#define CONV_X_BLKS   ((M_TOTAL * D_MODEL) / 1024)   // 8192
#define CONV_B_BLKS   ((NQKV * D_MODEL) / 1024)      // 3072
#define CONV_WO_BLKS  ((D_MODEL * D_MODEL) / 1024)   // 1024
#define CONV_BLKS     (CONV_X_BLKS + CONV_B_BLKS + CONV_WO_BLKS)

__global__ __launch_bounds__(256) void conv_all(
    const float* __restrict__ x,
    const float* __restrict__ Wq, const float* __restrict__ bq,
    const float* __restrict__ Wk, const float* __restrict__ bk,
    const float* __restrict__ Wv, const float* __restrict__ bv,
    const float* __restrict__ Wo)
{
    const int b = blockIdx.x;
    if (b < CONV_X_BLKS) {
        size_t i = ((size_t)b * 256 + threadIdx.x) * 4;
        float4 v = *reinterpret_cast<const float4*>(x + i);
        uint2 o;
        o.x = pack_h2(v.x, v.y);
        o.y = pack_h2(v.z, v.w);
        *reinterpret_cast<uint2*>(g_X + i) = o;
    } else if (b < CONV_X_BLKS + CONV_B_BLKS) {
        size_t j = ((size_t)(b - CONV_X_BLKS) * 256 + threadIdx.x) * 4;
        const int e = (int)(j & 63);
        const int k = (int)((j >> 6) & 1023);
        const int h = (int)((j >> 16) & 15);
        const int proj = (int)(j >> 20);
        const float* W = (proj == 0) ? Wq : (proj == 1) ? Wk : Wv;
        float4 v = *reinterpret_cast<const float4*>(
            W + (((size_t)h * D_MODEL + k) << 6) + e);
        const int n = proj * 1024 + h * 64 + e;
        uint2 o;
        o.x = pack_h2(v.x, v.y);
        o.y = pack_h2(v.z, v.w);
        *reinterpret_cast<uint2*>(g_Bqkv + (size_t)k * NQKV + n) = o;
        if (k == 0) {
            const float* bb = (proj == 0) ? bq : (proj == 1) ? bk : bv;
            #pragma unroll
            for (int jj = 0; jj < 4; jj++)
                g_bias_qkv[n + jj] = bb[h * 64 + e + jj];
        }
    } else {
        size_t i = ((size_t)(b - CONV_X_BLKS - CONV_B_BLKS) * 256 + threadIdx.x) * 4;
        float4 v = *reinterpret_cast<const float4*>(Wo + i);
        uint2 o;
        o.x = pack_h2(v.x, v.y);
        o.y = pack_h2(v.z, v.w);
        *reinterpret_cast<uint2*>(g_Wo2 + i) = o;
    }
}

// ============================================================================
// GEMM on mma.sync, single-pass fp16, 2-stage cp.async, BK=64.
// kc loop manually unrolled 2x: compile-time stage addressing.
// ============================================================================
#define AST 72
#define BST 136
#define MMS_A 0
#define MMS_B 9216
#define STAGE_EL (9216 + 8704)
#define MM_SMEM  (2 * STAGE_EL * 2)       // 71680 B per CTA

// Q pre-scale: 1/sqrt(64) * log2(e)
#define QSCALE 0.18033688011112042f

__global__ __launch_bounds__(256, 2) void mm_mma(const float* __restrict__ bias_ext,
                                                 float* __restrict__ outp, int mode) {
    extern __shared__ __align__(16) __half smm[];
    const unsigned sbase = smem_u32(smm);
    const int tid = threadIdx.x;
    const int lane = tid & 31;
    const int w = tid >> 5;
    const int mw = w >> 2, nw = w & 3;
    const int n0 = blockIdx.x * 128;
    const int m0 = blockIdx.y * 128;

    const __half* __restrict__ Ag = (mode == 1) ? g_X : g_A2;
    const __half* __restrict__ Bg = (mode == 1) ? g_Bqkv : g_Wo2;
    const int bw = (mode == 1) ? NQKV : D_MODEL;
    const float* __restrict__ bias = (mode == 1) ? g_bias_qkv : bias_ext;

    float acc[4][4][4];
    #pragma unroll
    for (int a = 0; a < 4; a++)
        #pragma unroll
        for (int bq_ = 0; bq_ < 4; bq_++)
            #pragma unroll
            for (int c = 0; c < 4; c++) acc[a][bq_][c] = 0.f;

    const int g = lane >> 3;
    const int a_row = tid >> 3, a_slot = tid & 7;
    const int b_row = tid >> 4, b_slot = tid & 15;

    auto issue = [&](int kc, unsigned sst) {
        const int k0 = kc * 64;
        #pragma unroll
        for (int i = 0; i < 4; i++) {
            {
                const int row = a_row + 32 * i;
                const unsigned so = 2u * (row * AST + a_slot * 8);
                const size_t ga = (size_t)(m0 + row) * D_MODEL + k0 + a_slot * 8;
                cp_async16(sst + 2u * MMS_A + so, Ag + ga);
            }
            {
                const int row = b_row + 16 * i;
                const unsigned so = 2u * (row * BST + b_slot * 8);
                const size_t gb = (size_t)(k0 + row) * bw + n0 + b_slot * 8;
                cp_async16(sst + 2u * MMS_B + so, Bg + gb);
            }
        }
        CP_COMMIT();
    };

    auto compute = [&](unsigned sst) {
        #pragma unroll
        for (int ks = 0; ks < 4; ks++) {
            unsigned ah[4][4], bh[4][2];
            const int arow = mw * 64 + (lane & 15);
            const int acol = ks * 16 + (lane >> 4) * 8;
            #pragma unroll
            for (int mt = 0; mt < 4; mt++) {
                const unsigned off = 2u * ((arow + mt * 16) * AST + acol);
                ldm_x4(ah[mt], sst + 2 * MMS_A + off);
            }
            const int kr = ks * 16 + (g & 1) * 8 + (lane & 7);
            #pragma unroll
            for (int np = 0; np < 2; np++) {
                const unsigned off = 2u * (kr * BST + nw * 32 + np * 16 + (g >> 1) * 8);
                ldm_x4_t(&bh[np * 2][0], sst + 2 * MMS_B + off);
            }
            #pragma unroll
            for (int mt = 0; mt < 4; mt++)
                #pragma unroll
                for (int nt = 0; nt < 4; nt++)
                    mma16816h(acc[mt][nt], ah[mt], bh[nt]);
        }
    };

    const unsigned st0 = sbase;
    const unsigned st1 = sbase + (unsigned)(2 * STAGE_EL);

    issue(0, st0);
    #pragma unroll 1
    for (int kc = 0; kc < 16; kc += 2) {
        CP_WAIT(0);
        __syncthreads();
        if (kc + 1 < 16) issue(kc + 1, st1);
        compute(st0);
        if (kc + 1 < 16) {
            CP_WAIT(0);
            __syncthreads();
            if (kc + 2 < 16) issue(kc + 2, st0);
            compute(st1);
        }
    }

    // Epilogue
    #pragma unroll
    for (int mt = 0; mt < 4; mt++) {
        const int r0 = m0 + mw * 64 + mt * 16 + (lane >> 2);
        #pragma unroll
        for (int nt = 0; nt < 4; nt++) {
            const int c = n0 + nw * 32 + nt * 8 + (lane & 3) * 2;
            const float b0 = bias[c], b1 = bias[c + 1];
            #pragma unroll
            for (int h2 = 0; h2 < 2; h2++) {
                const int r = r0 + h2 * 8;
                float v0 = acc[mt][nt][h2 * 2 + 0] + b0;
                float v1 = acc[mt][nt][h2 * 2 + 1] + b1;
                if (mode == 0) {
                    float2 vv = make_float2(v0, v1);
                    *reinterpret_cast<float2*>(outp + (size_t)r * D_MODEL + c) = vv;
                } else {
                    const int proj = c >> 10, nc = c & 1023, hh = nc >> 6, e = nc & 63;
                    const size_t idx =
                        (((size_t)((r >> 11) * NUM_HEADS + hh)) * SEQ + (r & 2047)) * HEAD_DIM + e;
                    if (proj == 0) {
                        *reinterpret_cast<unsigned*>(g_q + idx) =
                            pack_h2(v0 * QSCALE, v1 * QSCALE);
                    } else if (proj == 1) {
                        *reinterpret_cast<unsigned*>(g_k + idx) = pack_h2(v0, v1);
                    } else {
                        *reinterpret_cast<unsigned*>(g_v + idx) = pack_h2(v0, v1);
                    }
                }
            }
        }
    }
}

// ============================================================================
// Flash attention, FA2-style, 2 CTAs/SM: 128 q-rows x 64-key tiles.
// (R15 structure: one K+V commit group, one barrier per tile)
// exp via ex2.approx; m,l tracked in log2 domain (log2e folded into Q).
// ============================================================================
#define TST 72
#define AQ 0
#define AK(s) (9216 + (s) * 4608)
#define AV(s) (18432 + (s) * 4608)
#define ATTN_SMEM (27648 * 2)   // 55296 B

__global__ __launch_bounds__(256, 2) void attn_mma() {
    extern __shared__ __align__(16) __half smm[];
    const unsigned sbase = smem_u32(smm);
    const int tid = threadIdx.x;
    const int lane = tid & 31;
    const int w = tid >> 5;
    const int q0 = blockIdx.x * 128;
    const int bh = blockIdx.y;
    const size_t gbase = (size_t)bh * SEQ * HEAD_DIM;

    const int g = lane >> 3;
    const int browo = (g >> 1) * 8 + (lane & 7);
    const int bko = (g & 1) * 8;

    auto issueKV = [&](int kt2) {
        const int t0 = kt2 * 64;
        const int s = kt2 & 1;
        #pragma unroll
        for (int i = 0; i < 2; i++) {
            const int t = tid + 256 * i;
            const int row = t >> 3, slot = t & 7;
            const unsigned so = 2u * (row * TST + slot * 8);
            const size_t gk = gbase + (size_t)(t0 + row) * HEAD_DIM + slot * 8;
            cp_async16(sbase + 2u * AK(s) + so, g_k + gk);
            cp_async16(sbase + 2u * AV(s) + so, g_v + gk);
        }
        CP_COMMIT();
    };

    issueKV(0);

    // stage Q into smem
    #pragma unroll
    for (int i = 0; i < 4; i++) {
        const int t = tid + 256 * i;
        const int row = t >> 3, slot = t & 7;
        const int so = row * TST + slot * 8;
        const size_t gq = gbase + (size_t)(q0 + row) * HEAD_DIM + slot * 8;
        *reinterpret_cast<float4*>(smm + AQ + so) = *reinterpret_cast<const float4*>(g_q + gq);
    }
    __syncthreads();

    // warp's Q fragments (persistent in registers)
    unsigned qf[4][4];
    {
        const int arow = w * 16 + (lane & 15);
        #pragma unroll
        for (int ks = 0; ks < 4; ks++) {
            const unsigned qoff = 2u * (arow * TST + ks * 16 + (lane >> 4) * 8);
            ldm_x4(qf[ks], sbase + 2 * AQ + qoff);
        }
    }

    float m_run[2] = {-INFINITY, -INFINITY};   // log2 domain
    float l_run[2] = {0.f, 0.f};
    float oacc[8][4];
    #pragma unroll
    for (int a = 0; a < 8; a++)
        #pragma unroll
        for (int c = 0; c < 4; c++) oacc[a][c] = 0.f;

    for (int kt = 0; kt < 32; kt++) {
        CP_WAIT(0);        // K[kt] and V[kt] landed (one group)
        __syncthreads();   // visible; prev-tile smem fully consumed

        if (kt < 31) issueKV(kt + 1);   // overlaps S + softmax + PV

        const unsigned sk = sbase + 2u * AK(kt & 1);
        const unsigned sv = sbase + 2u * AV(kt & 1);

        // ---- S = Q K^T : 8 n8-tiles over 64 keys ----
        float sacc[8][4];
        #pragma unroll
        for (int a = 0; a < 8; a++)
            #pragma unroll
            for (int c = 0; c < 4; c++) sacc[a][c] = 0.f;

        #pragma unroll
        for (int ks = 0; ks < 4; ks++) {
            #pragma unroll
            for (int kb = 0; kb < 4; kb++) {
                unsigned kh4[4];
                const unsigned off = 2u * ((kb * 16 + browo) * TST + ks * 16 + bko);
                ldm_x4(kh4, sk + off);
                #pragma unroll
                for (int j = 0; j < 2; j++)
                    mma16816h(sacc[kb * 2 + j], qf[ks], &kh4[2 * j]);
            }
        }

        // ---- softmax (log2 domain, ex2; registers + quad shuffles) ----
        float mx0 = -INFINITY, mx1 = -INFINITY;
        #pragma unroll
        for (int nt = 0; nt < 8; nt++) {
            mx0 = fmaxf(mx0, fmaxf(sacc[nt][0], sacc[nt][1]));
            mx1 = fmaxf(mx1, fmaxf(sacc[nt][2], sacc[nt][3]));
        }
        mx0 = fmaxf(mx0, __shfl_xor_sync(0xffffffffu, mx0, 1));
        mx0 = fmaxf(mx0, __shfl_xor_sync(0xffffffffu, mx0, 2));
        mx1 = fmaxf(mx1, __shfl_xor_sync(0xffffffffu, mx1, 1));
        mx1 = fmaxf(mx1, __shfl_xor_sync(0xffffffffu, mx1, 2));
        const float mn0 = fmaxf(m_run[0], mx0);
        const float mn1 = fmaxf(m_run[1], mx1);
        const float al0 = ex2(m_run[0] - mn0);
        const float al1 = ex2(m_run[1] - mn1);
        m_run[0] = mn0; m_run[1] = mn1;

        unsigned ph[4][4];
        float s0 = 0.f, s1 = 0.f;
        #pragma unroll
        for (int kb = 0; kb < 4; kb++) {
            #pragma unroll
            for (int j = 0; j < 2; j++) {
                const int nt = kb * 2 + j;
                const float p0 = ex2(sacc[nt][0] - mn0);
                const float p1 = ex2(sacc[nt][1] - mn0);
                const float p2 = ex2(sacc[nt][2] - mn1);
                const float p3 = ex2(sacc[nt][3] - mn1);
                s0 += p0 + p1;
                s1 += p2 + p3;
                ph[kb][2 * j + 0] = pack_h2(p0, p1);
                ph[kb][2 * j + 1] = pack_h2(p2, p3);
            }
        }
        s0 += __shfl_xor_sync(0xffffffffu, s0, 1);
        s0 += __shfl_xor_sync(0xffffffffu, s0, 2);
        s1 += __shfl_xor_sync(0xffffffffu, s1, 1);
        s1 += __shfl_xor_sync(0xffffffffu, s1, 2);
        l_run[0] = l_run[0] * al0 + s0;
        l_run[1] = l_run[1] * al1 + s1;
        #pragma unroll
        for (int ot = 0; ot < 8; ot++) {
            oacc[ot][0] *= al0; oacc[ot][1] *= al0;
            oacc[ot][2] *= al1; oacc[ot][3] *= al1;
        }

        // ---- O += P V (V already resident) ----
        #pragma unroll
        for (int ks = 0; ks < 4; ks++) {
            const int kr = ks * 16 + (g & 1) * 8 + (lane & 7);
            #pragma unroll
            for (int eb = 0; eb < 4; eb++) {
                unsigned vh4[4];
                const unsigned voff = 2u * (kr * TST + eb * 16 + (g >> 1) * 8);
                ldm_x4_t(vh4, sv + voff);
                #pragma unroll
                for (int j = 0; j < 2; j++)
                    mma16816h(oacc[eb * 2 + j], ph[ks], &vh4[2 * j]);
            }
        }
    }

    // Epilogue: normalize, write single-fp16 A2 (concat layout)
    const int bb = bh >> 4, hh = bh & 15;
    const int r0 = w * 16 + (lane >> 2);
    const float inv0 = 1.f / l_run[0];
    const float inv1 = 1.f / l_run[1];
    const size_t mrow0 = ((size_t)bb * SEQ + q0 + r0) * D_MODEL + hh * HEAD_DIM;
    const size_t mrow1 = ((size_t)bb * SEQ + q0 + r0 + 8) * D_MODEL + hh * HEAD_DIM;
    #pragma unroll
    for (int ot = 0; ot < 8; ot++) {
        const int e = ot * 8 + (lane & 3) * 2;
        *reinterpret_cast<unsigned*>(g_A2 + mrow0 + e) =
            pack_h2(oacc[ot][0] * inv0, oacc[ot][1] * inv0);
        *reinterpret_cast<unsigned*>(g_A2 + mrow1 + e) =
            pack_h2(oacc[ot][2] * inv1, oacc[ot][3] * inv1);
    }
}

// ============================================================================
extern "C" void kernel_launch(void* const* d_in, const int* in_sizes, int n_in,
                              void* d_out, int out_size)
{
    const float* x  = (const float*)d_in[0];
    const float* Wq = (const float*)d_in[1];
    const float* bq = (const float*)d_in[2];
    const float* Wk = (const float*)d_in[3];
    const float* bk = (const float*)d_in[4];
    const float* Wv = (const float*)d_in[5];
    const float* bv = (const float*)d_in[6];
    const float* Wo = (const float*)d_in[7];
    const float* bo = (const float*)d_in[8];
    float* out = (float*)d_out;

    cudaFuncSetAttribute(mm_mma, cudaFuncAttributeMaxDynamicSharedMemorySize, MM_SMEM);
    cudaFuncSetAttribute(attn_mma, cudaFuncAttributeMaxDynamicSharedMemorySize, ATTN_SMEM);

    conv_all<<<CONV_BLKS, 256>>>(x, Wq, bq, Wk, bk, Wv, bv, Wo);

    mm_mma<<<dim3(NQKV / 128, M_TOTAL / 128), 256, MM_SMEM>>>(nullptr, nullptr, 1);
    attn_mma<<<dim3(SEQ / 128, NBH), 256, ATTN_SMEM>>>();
    mm_mma<<<dim3(D_MODEL / 128, M_TOTAL / 128), 256, MM_SMEM>>>(bo, out, 0);
}